// round 8
// baseline (speedup 1.0000x reference)
#include <cuda_runtime.h>

// Problem constants
#define Bdim 4
#define Cdim 16
#define Ldim 512
#define Hdim 1024

#define NBLK  592u     // persistent grid: 4 blocks/SM x 148 SM
#define NSLOT 6144u    // 4096 dot tasks + 2048 add tiles

// Scratch: [2][B][L][C] floats, channel contiguous. 256 KB (L2 resident).
__device__ float g_scratch[2 * Bdim * Ldim * Cdim];

// Progress counters. g_done[t][b] -> 512 when all dot tasks of (tensor,b) done.
// g_addcnt[b] counts completed add tiles; the 512th resets the batch's counters.
__device__ int g_done[2][Bdim];
__device__ int g_addcnt[Bdim];

// ---------------------------------------------------------------------------
// Dot task id in [0,4096): b = id>>10, w = id&1023, t = w>>9,
// c = (w>>5)&15, lchunk = w&31. Block (8 warps x 2 rows) covers rows
// [lchunk*16, +16) of (t,b,c). Round-2 inner loop (best measured).
// ---------------------------------------------------------------------------
__device__ __forceinline__ void dot_task(
    unsigned id, const float* __restrict__ start,
    const float* __restrict__ end, const float* __restrict__ v)
{
    const unsigned tid  = threadIdx.x;
    const unsigned wid  = tid >> 5;
    const unsigned lane = tid & 31;

    const unsigned b      = id >> 10;
    const unsigned w      = id & 1023;
    const unsigned t      = w >> 9;
    const unsigned c      = (w >> 5) & 15;
    const unsigned lchunk = w & 31;
    const unsigned l      = lchunk * 16 + wid * 2;

    const float* base = t ? end : start;
    const float4* row0 =
        (const float4*)(base + (size_t)((b * Cdim + c) * Ldim + l) * Hdim);
    const float4* v4 = (const float4*)(v + t * Hdim);
    const unsigned RS = Hdim / 4;

    float s0 = 0.f, s1 = 0.f;
#pragma unroll
    for (int k = 0; k < 8; k++) {
        const unsigned o = lane + 32 * k;
        float4 a0 = __ldcs(&row0[o]);
        float4 a1 = __ldcs(&row0[o + RS]);
        float4 wv = v4[o];
        s0 += a0.x * wv.x + a0.y * wv.y + a0.z * wv.z + a0.w * wv.w;
        s1 += a1.x * wv.x + a1.y * wv.y + a1.z * wv.z + a1.w * wv.w;
    }
#pragma unroll
    for (int o = 16; o; o >>= 1) {
        s0 += __shfl_xor_sync(0xFFFFFFFFu, s0, o);
        s1 += __shfl_xor_sync(0xFFFFFFFFu, s1, o);
    }
    if (lane == 0) {
        float* dst = &g_scratch[((t * Bdim + b) * Ldim + l) * Cdim + c];
        dst[0]    = s0;
        dst[Cdim] = s1;
    }
    __syncthreads();                      // all warps' scratch stores done
    if (tid == 0) {
        __threadfence();                  // publish (cumulative w/ bar.cta)
        atomicAdd(&g_done[t][b], 1);
    }
}

// ---------------------------------------------------------------------------
// Add tile id in [0,2048): b = id>>9, jt = id&7, it = (id>>3)&63.
// Gated on both tensors of batch b complete. Round-2 tile body.
// ---------------------------------------------------------------------------
__device__ __forceinline__ void add_task(
    unsigned id, float4* __restrict__ out, float4* e_sm, float4* s_sm)
{
    const unsigned tid = threadIdx.x;
    const unsigned b   = id >> 9;
    const unsigned loc = id & 511;
    const unsigned jt  = loc & 7;
    const unsigned it  = loc >> 3;

    if (tid == 0) {
        volatile int* d0 = &g_done[0][b];
        volatile int* d1 = &g_done[1][b];
        while (*d0 < 512 || *d1 < 512)
            __nanosleep(64);
        __threadfence();                  // acquire
    }
    __syncthreads();

    const float4* sc4 = (const float4*)g_scratch;  // [2][B][L][4] float4
    e_sm[tid] = sc4[((Bdim + b) * Ldim + jt * 64) * (Cdim / 4) + tid];
    if (tid < 32)
        s_sm[tid] = sc4[(b * Ldim + it * 8) * (Cdim / 4) + tid];
    __syncthreads();

    const unsigned q = tid & 3;
    const unsigned j = tid >> 2;
    const float4 e = e_sm[j * 4 + q];

    float4* dst = &out[(((b * Ldim + it * 8) * Ldim) + jt * 64 + j) * 4 + q];
#pragma unroll
    for (int i = 0; i < 8; i++) {
        float4 s = s_sm[i * 4 + q];
        dst[(size_t)i * Ldim * 4] =
            make_float4(s.x + e.x, s.y + e.y, s.z + e.z, s.w + e.w);
    }
    __syncthreads();                      // smem safe for next task
    if (tid == 0) {
        if (atomicAdd(&g_addcnt[b], 1) == 511) {   // last add of batch b
            g_done[0][b] = 0;             // self-reset for graph replay
            g_done[1][b] = 0;
            g_addcnt[b]  = 0;
        }
    }
}

// ---------------------------------------------------------------------------
// Persistent fused kernel. Slot sequence (every add's producers occupy
// strictly smaller slots -> deadlock-free under per-block in-order strides):
//   [0,2048):      dot ids 0..2047            (batches 0,1)
//   [2048,5632):   512 groups of 7: r<4 -> dot id 2048+4g+r (batches 2,3)
//                                   r>=4 -> add id 3g+(r-4)  (batches 0..2)
//   [5632,6144):   add ids 1536..2047          (batch 3)
// ---------------------------------------------------------------------------
__global__ void __launch_bounds__(256, 4) fused_kernel(
    const float* __restrict__ start,
    const float* __restrict__ end,
    const float* __restrict__ v,
    float4* __restrict__ out)
{
    __shared__ float4 e_sm[64 * 4];
    __shared__ float4 s_sm[8 * 4];

    for (unsigned slot = blockIdx.x; slot < NSLOT; slot += NBLK) {
        if (slot < 2048u) {
            dot_task(slot, start, end, v);
        } else if (slot < 5632u) {
            const unsigned x = slot - 2048u;
            const unsigned g = x / 7u;
            const unsigned r = x % 7u;
            if (r < 4u)
                dot_task(2048u + 4u * g + r, start, end, v);
            else
                add_task(3u * g + (r - 4u), out, e_sm, s_sm);
        } else {
            add_task(1536u + (slot - 5632u), out, e_sm, s_sm);
        }
    }
}

extern "C" void kernel_launch(void* const* d_in, const int* in_sizes, int n_in,
                              void* d_out, int out_size)
{
    const float* start = (const float*)d_in[0];
    const float* end   = (const float*)d_in[1];
    const float* v     = (const float*)d_in[2];
    float4* out = (float4*)d_out;

    fused_kernel<<<NBLK, 256>>>(start, end, v, out);
}